// round 6
// baseline (speedup 1.0000x reference)
#include <cuda_runtime.h>
#include <cstdint>

// ============================ problem constants ============================
#define Bn      8
#define Np      16384
#define MCc     2048
#define KNNk    32
#define EMBc    256
#define MT      4                 // m-tiles per group (M = 128 rows)
#define NGROUPS (Bn * MCc / MT)   // 4096
#define GRID    152
#define NT      512

// SMEM layout in floats. h stride padded so (stride mod 8) == 4:
// fragment loads hit banks (4*gp + tg) -> conflict-free.
#define PK2 132                   // K stride for h (and W3): 128 + 4
#define S_W3 0                    // [256][132] tf32
#define S_H  (S_W3 + 256 * PK2)   // [128][132] h1 (cols 0..63) / h2 (0..127)
#define S_B2 (S_H + 128 * PK2)    // 128
#define S_W1 (S_B2 + 128)         // 192
#define S_B1 (S_W1 + 192)         // 64
#define S_TOT (S_B1 + 64)
#define SMEM_BYTES (S_TOT * 4)    // 204288 B

// Pre-converted tf32 W2 [n=128][k=64] (32 KB, L2/L1 resident; no allocation).
__device__ uint32_t g_W2tf[128 * 64];

// ============================ PTX helpers ============================
__device__ __forceinline__ uint32_t cvt_tf32(float f) {
    uint32_t r;
    asm("cvt.rna.tf32.f32 %0, %1;" : "=r"(r) : "f"(f));
    return r;
}

// D = A*B + D,  m16n8k8, A row-major tf32, B col-major tf32, fp32 accum.
__device__ __forceinline__ void mma8(float* d,
                                     const uint32_t* a,
                                     uint32_t b0, uint32_t b1) {
    asm volatile(
        "mma.sync.aligned.m16n8k8.row.col.f32.tf32.tf32.f32 "
        "{%0,%1,%2,%3}, {%4,%5,%6,%7}, {%8,%9}, {%0,%1,%2,%3};"
        : "+f"(d[0]), "+f"(d[1]), "+f"(d[2]), "+f"(d[3])
        : "r"(a[0]), "r"(a[1]), "r"(a[2]), "r"(a[3]), "r"(b0), "r"(b1));
}

__global__ void prep_w2(const float* __restrict__ W2) {
    int i = blockIdx.x * blockDim.x + threadIdx.x;
    if (i < 128 * 64) g_W2tf[i] = cvt_tf32(W2[i]);
}

// ============================ kernel ============================
__global__ __launch_bounds__(NT, 1)
void patch_embed_mma(const float* __restrict__ xyz,
                     const float* __restrict__ centers,
                     const int*   __restrict__ idx_knn,
                     const float* __restrict__ W1,
                     const float* __restrict__ b1,
                     const float* __restrict__ b2,
                     const float* __restrict__ W3,
                     const float* __restrict__ b3,
                     float*       __restrict__ out)
{
    extern __shared__ __align__(16) float sm[];
    uint32_t* sW3u = reinterpret_cast<uint32_t*>(sm + S_W3);
    uint32_t* sHu  = reinterpret_cast<uint32_t*>(sm + S_H);
    float*    sB2  = sm + S_B2;
    float*    sW1v = sm + S_W1;
    float*    sB1v = sm + S_B1;

    const int tid  = threadIdx.x;
    const int wid  = tid >> 5;
    const int lane = tid & 31;
    const int gp   = lane >> 2;   // fragment group (row within 8-row band)
    const int tg   = lane & 3;    // thread-in-group (k within 4)

    // warp tiling: mtp = 32-row quarter (== m_local), nq = n quarter
    const int mtp = wid & 3;
    const int nq  = wid >> 2;

    // ---- one-time staging (tf32-rounded W3) --------------------------------
    for (int i = tid; i < 256 * 128; i += NT) {       // W3 [n=256][k=128]
        int n = i >> 7, k = i & 127;
        sW3u[n * PK2 + k] = cvt_tf32(W3[i]);
    }
    if (tid < 192) sW1v[tid] = W1[tid];
    if (tid < 64)  sB1v[tid] = b1[tid];
    if (tid < 128) sB2[tid]  = b2[tid];
    __syncthreads();

    for (int g = blockIdx.x; g < NGROUPS; g += GRID) {
        const int bm0 = g * MT;

        // ---- layer 1: gather + 3->64 relu -> h1 (rows 0..127, cols 0..63) --
        {
            const int row = tid & 127;                // m_local*32 + k
            const int cb  = (tid >> 7) * 16;          // 16-channel block
            const int bm  = bm0 + (row >> 5);
            const int kk  = row & 31;
            const int ii  = __ldg(&idx_knn[bm * KNNk + kk]);
            const float* p = xyz + ((size_t)(bm >> 11) * Np + ii) * 3;
            const float x = p[0] - __ldg(&centers[bm * 3 + 0]);
            const float y = p[1] - __ldg(&centers[bm * 3 + 1]);
            const float z = p[2] - __ldg(&centers[bm * 3 + 2]);

            uint32_t hv[16];
            #pragma unroll
            for (int o = 0; o < 16; ++o) {
                const int oo = cb + o;
                float v = sB1v[oo];
                v = fmaf(sW1v[oo * 3 + 0], x, v);
                v = fmaf(sW1v[oo * 3 + 1], y, v);
                v = fmaf(sW1v[oo * 3 + 2], z, v);
                hv[o] = cvt_tf32(fmaxf(v, 0.f));
            }
            uint32_t* h1r = sHu + row * PK2 + cb;     // 16B-aligned
            #pragma unroll
            for (int j = 0; j < 4; ++j)
                *reinterpret_cast<uint4*>(h1r + 4 * j) =
                    make_uint4(hv[4*j], hv[4*j+1], hv[4*j+2], hv[4*j+3]);
        }
        __syncthreads();

        // ---- GEMM1: D1[128x128] = h1[128x64] * W2^T ------------------------
        // warp: 2 m16-tiles (rows 32*mtp..) x 4 n8-tiles (cols nq*32..)
        {
            float acc1[2][4][4];
            #pragma unroll
            for (int m = 0; m < 2; ++m)
                #pragma unroll
                for (int nt = 0; nt < 4; ++nt)
                    #pragma unroll
                    for (int j = 0; j < 4; ++j) acc1[m][nt][j] = 0.f;

            #pragma unroll
            for (int ks = 0; ks < 8; ++ks) {
                const int k0 = ks * 8;
                uint32_t a[2][4];
                #pragma unroll
                for (int m = 0; m < 2; ++m) {
                    const uint32_t* hr = sHu + (mtp*32 + m*16 + gp) * PK2 + k0 + tg;
                    a[m][0] = hr[0];
                    a[m][1] = hr[8 * PK2];
                    a[m][2] = hr[4];
                    a[m][3] = hr[8 * PK2 + 4];
                }
                #pragma unroll
                for (int nt = 0; nt < 4; ++nt) {
                    const uint32_t* wr = g_W2tf + (nq*32 + nt*8 + gp) * 64 + k0 + tg;
                    const uint32_t b0v = __ldg(wr), b1v = __ldg(wr + 4);
                    mma8(acc1[0][nt], a[0], b0v, b1v);
                    mma8(acc1[1][nt], a[1], b0v, b1v);
                }
            }
            __syncthreads();   // all h1 reads done before h2 overwrites

            // ---- epilogue 1: h2 = tf32(relu(D1 + b2)) ----------------------
            #pragma unroll
            for (int m = 0; m < 2; ++m) {
                const int r0 = mtp*32 + m*16 + gp;
                #pragma unroll
                for (int nt = 0; nt < 4; ++nt) {
                    const int c0 = nq*32 + nt*8 + 2*tg;
                    const float bb0 = sB2[c0], bb1 = sB2[c0 + 1];
                    uint2 lo, hi;
                    lo.x = cvt_tf32(fmaxf(acc1[m][nt][0] + bb0, 0.f));
                    lo.y = cvt_tf32(fmaxf(acc1[m][nt][1] + bb1, 0.f));
                    hi.x = cvt_tf32(fmaxf(acc1[m][nt][2] + bb0, 0.f));
                    hi.y = cvt_tf32(fmaxf(acc1[m][nt][3] + bb1, 0.f));
                    *reinterpret_cast<uint2*>(sHu + r0 * PK2 + c0)       = lo;
                    *reinterpret_cast<uint2*>(sHu + (r0 + 8) * PK2 + c0) = hi;
                }
            }
        }
        __syncthreads();

        // ---- GEMM2: D2[128x256] = h2[128x128] * W3^T -----------------------
        // warp: 2 m16-tiles (one m_local) x 8 n8-tiles (cols nq*64..)
        {
            float acc2[2][8][4];
            #pragma unroll
            for (int m = 0; m < 2; ++m)
                #pragma unroll
                for (int nt = 0; nt < 8; ++nt)
                    #pragma unroll
                    for (int j = 0; j < 4; ++j) acc2[m][nt][j] = 0.f;

            #pragma unroll
            for (int ks = 0; ks < 16; ++ks) {
                const int k0 = ks * 8;
                uint32_t a[2][4];
                #pragma unroll
                for (int m = 0; m < 2; ++m) {
                    const uint32_t* hr = sHu + (mtp*32 + m*16 + gp) * PK2 + k0 + tg;
                    a[m][0] = hr[0];
                    a[m][1] = hr[8 * PK2];
                    a[m][2] = hr[4];
                    a[m][3] = hr[8 * PK2 + 4];
                }
                #pragma unroll
                for (int nt = 0; nt < 8; ++nt) {
                    const uint32_t* wr = sW3u + (nq*64 + nt*8 + gp) * PK2 + k0 + tg;
                    const uint32_t b0v = wr[0], b1v = wr[4];
                    mma8(acc2[0][nt], a[0], b0v, b1v);
                    mma8(acc2[1][nt], a[1], b0v, b1v);
                }
            }

            // ---- max over the 32 k-rows of this warp's m_local + b3 + store
            // Thread holds rows {gp, gp+8, gp+16, gp+24}; butterfly over gp
            // (xor 4,8,16) completes the 32-row max.
            const int bm = bm0 + mtp;
            #pragma unroll
            for (int nt = 0; nt < 8; ++nt) {
                float m0 = fmaxf(fmaxf(acc2[0][nt][0], acc2[0][nt][2]),
                                 fmaxf(acc2[1][nt][0], acc2[1][nt][2]));
                float m1 = fmaxf(fmaxf(acc2[0][nt][1], acc2[0][nt][3]),
                                 fmaxf(acc2[1][nt][1], acc2[1][nt][3]));
                #pragma unroll
                for (int s = 4; s < 32; s <<= 1) {
                    m0 = fmaxf(m0, __shfl_xor_sync(0xffffffffu, m0, s));
                    m1 = fmaxf(m1, __shfl_xor_sync(0xffffffffu, m1, s));
                }
                if (lane < 4) {
                    const int c = nq*64 + nt*8 + 2*tg;
                    float2 r2;
                    r2.x = m0 + __ldg(&b3[c]);
                    r2.y = m1 + __ldg(&b3[c + 1]);
                    *reinterpret_cast<float2*>(&out[(size_t)bm * EMBc + c]) = r2;
                }
            }
        }
        __syncthreads();   // GEMM2 reads of sH done before next layer-1 write
    }
}

// ============================ launch ============================
extern "C" void kernel_launch(void* const* d_in, const int* in_sizes, int n_in,
                              void* d_out, int out_size)
{
    // metadata order: xyz, centers, idx_knn, W1, b1, W2, b2, W3, b3
    const float* xyz     = (const float*)d_in[0];
    const float* centers = (const float*)d_in[1];
    const int*   idx_knn = (const int*)  d_in[2];
    const float* W1      = (const float*)d_in[3];
    const float* b1      = (const float*)d_in[4];
    const float* W2      = (const float*)d_in[5];
    const float* b2      = (const float*)d_in[6];
    const float* W3      = (const float*)d_in[7];
    const float* b3      = (const float*)d_in[8];
    float* out = (float*)d_out;

    // Idempotent attribute set (capture-safe, no allocation).
    cudaFuncSetAttribute(patch_embed_mma,
                         cudaFuncAttributeMaxDynamicSharedMemorySize,
                         SMEM_BYTES);

    prep_w2<<<(128 * 64 + 255) / 256, 256>>>(W2);
    patch_embed_mma<<<GRID, NT, SMEM_BYTES>>>(
        xyz, centers, idx_knn, W1, b1, b2, W3, b3, out);
}

// round 7
// speedup vs baseline: 1.0643x; 1.0643x over previous
#include <cuda_runtime.h>
#include <cstdint>

// ============================ problem constants ============================
#define Bn      8
#define Np      16384
#define MCc     2048
#define KNNk    32
#define EMBc    256
#define MT      4                 // m-tiles per group (M = 128 rows)
#define NGROUPS (Bn * MCc / MT)   // 4096
#define GRID    152
#define NT      512

// SMEM layout in floats. h stride padded so (stride mod 8) == 4:
// scalar frag loads hit banks (4*gp + tg); LDSM 8-row matrices hit banks
// 4r..4r+3 -> all 32 banks once. Conflict-free both ways.
#define PK2 132                   // K stride for h (and W3): 128 + 4
#define S_W3 0                    // [256][132] tf32
#define S_H  (S_W3 + 256 * PK2)   // [128][132] h1 (cols 0..63) / h2 (0..127)
#define S_B2 (S_H + 128 * PK2)    // 128
#define S_W1 (S_B2 + 128)         // 192
#define S_B1 (S_W1 + 192)         // 64
#define S_TOT (S_B1 + 64)
#define SMEM_BYTES (S_TOT * 4)    // 204288 B

// Pre-converted tf32 W2 [n=128][k=64] (32 KB, L2/L1 resident; no allocation).
__device__ uint32_t g_W2tf[128 * 64];

// ============================ PTX helpers ============================
__device__ __forceinline__ uint32_t cvt_tf32(float f) {
    uint32_t r;
    asm("cvt.rna.tf32.f32 %0, %1;" : "=r"(r) : "f"(f));
    return r;
}

// D = A*B + D,  m16n8k8, A row-major tf32, B col-major tf32, fp32 accum.
__device__ __forceinline__ void mma8(float* d,
                                     const uint32_t* a,
                                     uint32_t b0, uint32_t b1) {
    asm volatile(
        "mma.sync.aligned.m16n8k8.row.col.f32.tf32.tf32.f32 "
        "{%0,%1,%2,%3}, {%4,%5,%6,%7}, {%8,%9}, {%0,%1,%2,%3};"
        : "+f"(d[0]), "+f"(d[1]), "+f"(d[2]), "+f"(d[3])
        : "r"(a[0]), "r"(a[1]), "r"(a[2]), "r"(a[3]), "r"(b0), "r"(b1));
}

// ldmatrix x4 (b16 view): 4 consecutive 8x8-b16 (= 8x4-b32) matrices.
__device__ __forceinline__ void ldsm4(uint32_t* r, uint32_t addr) {
    asm volatile(
        "ldmatrix.sync.aligned.m8n8.x4.shared.b16 {%0,%1,%2,%3}, [%4];"
        : "=r"(r[0]), "=r"(r[1]), "=r"(r[2]), "=r"(r[3]) : "r"(addr));
}

__device__ __forceinline__ uint32_t smem_u32(const void* p) {
    uint32_t a;
    asm("{ .reg .u64 t; cvta.to.shared.u64 t, %1; cvt.u32.u64 %0, t; }"
        : "=r"(a) : "l"(p));
    return a;
}

__global__ void prep_w2(const float* __restrict__ W2) {
    int i = blockIdx.x * blockDim.x + threadIdx.x;
    if (i < 128 * 64) g_W2tf[i] = cvt_tf32(W2[i]);
}

// ============================ kernel ============================
__global__ __launch_bounds__(NT, 1)
void patch_embed_mma(const float* __restrict__ xyz,
                     const float* __restrict__ centers,
                     const int*   __restrict__ idx_knn,
                     const float* __restrict__ W1,
                     const float* __restrict__ b1,
                     const float* __restrict__ b2,
                     const float* __restrict__ W3,
                     const float* __restrict__ b3,
                     float*       __restrict__ out)
{
    extern __shared__ __align__(16) float sm[];
    uint32_t* sW3u = reinterpret_cast<uint32_t*>(sm + S_W3);
    uint32_t* sHu  = reinterpret_cast<uint32_t*>(sm + S_H);
    float*    sB2  = sm + S_B2;
    float*    sW1v = sm + S_W1;
    float*    sB1v = sm + S_B1;

    const int tid  = threadIdx.x;
    const int wid  = tid >> 5;
    const int lane = tid & 31;
    const int gp   = lane >> 2;
    const int tg   = lane & 3;

    // warp tiling: mtp = 32-row quarter (== m_local), nq = n quarter
    const int mtp = wid & 3;
    const int nq  = wid >> 2;

    // ---- one-time staging (tf32-rounded W3) --------------------------------
    for (int i = tid; i < 256 * 128; i += NT) {       // W3 [n=256][k=128]
        int n = i >> 7, k = i & 127;
        sW3u[n * PK2 + k] = cvt_tf32(W3[i]);
    }
    if (tid < 192) sW1v[tid] = W1[tid];
    if (tid < 64)  sB1v[tid] = b1[tid];
    if (tid < 128) sB2[tid]  = b2[tid];
    __syncthreads();

    // ---- precomputed LDSM base addresses (bytes) ---------------------------
    const uint32_t sH_b  = smem_u32(sHu);
    const uint32_t sW3_b = smem_u32(sW3u);
    // A matrices: rows mtp*32 + m*16 + (lane&15), k-half (lane>>4)*4
    uint32_t aAddr[2];
    #pragma unroll
    for (int m = 0; m < 2; ++m)
        aAddr[m] = sH_b +
            (((mtp*32 + m*16 + (lane & 15)) * PK2 + ((lane >> 4) << 2)) << 2);
    // B matrices (W3): n = nq*64 + p*16 + (lane&7) + ((lane>>4)<<3),
    //                  k-half ((lane>>3)&1)*4
    uint32_t bAddr[4];
    #pragma unroll
    for (int p = 0; p < 4; ++p)
        bAddr[p] = sW3_b +
            (((nq*64 + p*16 + (lane & 7) + ((lane >> 4) << 3)) * PK2
              + (((lane >> 3) & 1) << 2)) << 2);

    // ---- gather prefetch state (this thread's fixed row) -------------------
    const int row = tid & 127;                // m_local*32 + k
    const int cb  = (tid >> 7) * 16;          // 16-channel block
    const int kk  = row & 31;
    const int mo  = row >> 5;                 // m_local

    float px, py, pz;                         // prefetched local coords
    {
        const int bm = blockIdx.x * MT + mo;
        const int ii = __ldg(&idx_knn[bm * KNNk + kk]);
        const float* p = xyz + ((size_t)(bm >> 11) * Np + ii) * 3;
        px = p[0] - __ldg(&centers[bm * 3 + 0]);
        py = p[1] - __ldg(&centers[bm * 3 + 1]);
        pz = p[2] - __ldg(&centers[bm * 3 + 2]);
    }

    for (int g = blockIdx.x; g < NGROUPS; g += GRID) {
        const int bm0 = g * MT;
        const int gn  = (g + GRID < NGROUPS) ? (g + GRID) : g;  // clamp

        // ---- layer 1: 3->64 relu from prefetched coords -> h1 --------------
        {
            uint32_t hv[16];
            #pragma unroll
            for (int o = 0; o < 16; ++o) {
                const int oo = cb + o;
                float v = sB1v[oo];
                v = fmaf(sW1v[oo * 3 + 0], px, v);
                v = fmaf(sW1v[oo * 3 + 1], py, v);
                v = fmaf(sW1v[oo * 3 + 2], pz, v);
                hv[o] = cvt_tf32(fmaxf(v, 0.f));
            }
            uint32_t* h1r = sHu + row * PK2 + cb;
            #pragma unroll
            for (int j = 0; j < 4; ++j)
                *reinterpret_cast<uint4*>(h1r + 4 * j) =
                    make_uint4(hv[4*j], hv[4*j+1], hv[4*j+2], hv[4*j+3]);
        }
        // prefetch next group's knn index (long-latency; overlaps GEMM1)
        const int nbm = gn * MT + mo;
        const int nii = __ldg(&idx_knn[nbm * KNNk + kk]);
        __syncthreads();

        // ---- GEMM1: D1[128x128] = h1[128x64] * W2^T ------------------------
        {
            float acc1[2][4][4];
            #pragma unroll
            for (int m = 0; m < 2; ++m)
                #pragma unroll
                for (int nt = 0; nt < 4; ++nt)
                    #pragma unroll
                    for (int j = 0; j < 4; ++j) acc1[m][nt][j] = 0.f;

            #pragma unroll
            for (int ks = 0; ks < 8; ++ks) {
                const uint32_t k4 = (uint32_t)ks << 5;   // k0*4 bytes
                uint32_t a0[4], a1[4];
                ldsm4(a0, aAddr[0] + k4);
                ldsm4(a1, aAddr[1] + k4);
                const int k0 = ks * 8;
                #pragma unroll
                for (int nt = 0; nt < 4; ++nt) {
                    const uint32_t* wr = g_W2tf + (nq*32 + nt*8 + gp) * 64 + k0 + tg;
                    const uint32_t b0v = __ldg(wr), b1v = __ldg(wr + 4);
                    mma8(acc1[0][nt], a0, b0v, b1v);
                    mma8(acc1[1][nt], a1, b0v, b1v);
                }
            }
            __syncthreads();   // all h1 reads done before h2 overwrites

            // ---- epilogue 1: h2 = tf32(relu(D1 + b2)) ----------------------
            #pragma unroll
            for (int m = 0; m < 2; ++m) {
                const int r0 = mtp*32 + m*16 + gp;
                #pragma unroll
                for (int nt = 0; nt < 4; ++nt) {
                    const int c0 = nq*32 + nt*8 + 2*tg;
                    const float bb0 = sB2[c0], bb1 = sB2[c0 + 1];
                    uint2 lo, hi;
                    lo.x = cvt_tf32(fmaxf(acc1[m][nt][0] + bb0, 0.f));
                    lo.y = cvt_tf32(fmaxf(acc1[m][nt][1] + bb1, 0.f));
                    hi.x = cvt_tf32(fmaxf(acc1[m][nt][2] + bb0, 0.f));
                    hi.y = cvt_tf32(fmaxf(acc1[m][nt][3] + bb1, 0.f));
                    *reinterpret_cast<uint2*>(sHu + r0 * PK2 + c0)       = lo;
                    *reinterpret_cast<uint2*>(sHu + (r0 + 8) * PK2 + c0) = hi;
                }
            }
        }
        // prefetch next group's coords (overlaps GEMM2)
        {
            const float* p = xyz + ((size_t)(nbm >> 11) * Np + nii) * 3;
            px = p[0] - __ldg(&centers[nbm * 3 + 0]);
            py = p[1] - __ldg(&centers[nbm * 3 + 1]);
            pz = p[2] - __ldg(&centers[nbm * 3 + 2]);
        }
        __syncthreads();

        // ---- GEMM2: D2[128x256] = h2[128x128] * W3^T -----------------------
        {
            float acc2[2][8][4];
            #pragma unroll
            for (int m = 0; m < 2; ++m)
                #pragma unroll
                for (int nt = 0; nt < 8; ++nt)
                    #pragma unroll
                    for (int j = 0; j < 4; ++j) acc2[m][nt][j] = 0.f;

            #pragma unroll
            for (int ks = 0; ks < 16; ++ks) {
                const uint32_t k4 = (uint32_t)ks << 5;
                uint32_t a0[4], a1[4];
                ldsm4(a0, aAddr[0] + k4);
                ldsm4(a1, aAddr[1] + k4);
                #pragma unroll
                for (int p = 0; p < 4; ++p) {
                    uint32_t bf[4];
                    ldsm4(bf, bAddr[p] + k4);
                    mma8(acc2[0][2*p],     a0, bf[0], bf[1]);
                    mma8(acc2[1][2*p],     a1, bf[0], bf[1]);
                    mma8(acc2[0][2*p + 1], a0, bf[2], bf[3]);
                    mma8(acc2[1][2*p + 1], a1, bf[2], bf[3]);
                }
            }

            // ---- max over 32 k-rows of this warp's m_local + b3 + store ----
            const int bm = bm0 + mtp;
            #pragma unroll
            for (int nt = 0; nt < 8; ++nt) {
                float m0 = fmaxf(fmaxf(acc2[0][nt][0], acc2[0][nt][2]),
                                 fmaxf(acc2[1][nt][0], acc2[1][nt][2]));
                float m1 = fmaxf(fmaxf(acc2[0][nt][1], acc2[0][nt][3]),
                                 fmaxf(acc2[1][nt][1], acc2[1][nt][3]));
                #pragma unroll
                for (int s = 4; s < 32; s <<= 1) {
                    m0 = fmaxf(m0, __shfl_xor_sync(0xffffffffu, m0, s));
                    m1 = fmaxf(m1, __shfl_xor_sync(0xffffffffu, m1, s));
                }
                if (lane < 4) {
                    const int c = nq*64 + nt*8 + 2*tg;
                    float2 r2;
                    r2.x = m0 + __ldg(&b3[c]);
                    r2.y = m1 + __ldg(&b3[c + 1]);
                    *reinterpret_cast<float2*>(&out[(size_t)bm * EMBc + c]) = r2;
                }
            }
        }
        __syncthreads();   // GEMM2 reads of sH done before next layer-1 write
    }
}

// ============================ launch ============================
extern "C" void kernel_launch(void* const* d_in, const int* in_sizes, int n_in,
                              void* d_out, int out_size)
{
    // metadata order: xyz, centers, idx_knn, W1, b1, W2, b2, W3, b3
    const float* xyz     = (const float*)d_in[0];
    const float* centers = (const float*)d_in[1];
    const int*   idx_knn = (const int*)  d_in[2];
    const float* W1      = (const float*)d_in[3];
    const float* b1      = (const float*)d_in[4];
    const float* W2      = (const float*)d_in[5];
    const float* b2      = (const float*)d_in[6];
    const float* W3      = (const float*)d_in[7];
    const float* b3      = (const float*)d_in[8];
    float* out = (float*)d_out;

    // Idempotent attribute set (capture-safe, no allocation).
    cudaFuncSetAttribute(patch_embed_mma,
                         cudaFuncAttributeMaxDynamicSharedMemorySize,
                         SMEM_BYTES);

    prep_w2<<<(128 * 64 + 255) / 256, 256>>>(W2);
    patch_embed_mma<<<GRID, NT, SMEM_BYTES>>>(
        xyz, centers, idx_knn, W1, b1, b2, W3, b3, out);
}

// round 8
// speedup vs baseline: 1.2478x; 1.1724x over previous
#include <cuda_runtime.h>
#include <cuda_fp16.h>
#include <cstdint>

// ============================ problem constants ============================
#define Bn      8
#define Np      16384
#define MCc     2048
#define KNNk    32
#define EMBc    256
#define MT      4                 // m-tiles per group (M = 128 rows)
#define NGROUPS (Bn * MCc / MT)   // 4096
#define GRID    152
#define NT      512

// Strides in halfs, padded so (PK mod 64) == 8 -> row byte-stride mod 128
// == 16 -> ldmatrix 8-row sets conflict-free (banks 4r..4r+3 each).
#define PKH  136                  // h and W3 k-stride (K=128)
#define PKW2 72                   // W2 k-stride (K=64)

// SMEM byte offsets (all 16B aligned)
#define S_W3  0                              // [256][136] half: 69632 B
#define S_H   69632                          // [128][136] half: 34816 B
#define S_W2  104448                         // [128][72]  half: 18432 B
#define S_B2  122880                         // 128 f32
#define S_W1  123392                         // 192 f32
#define S_B1  124160                         // 64 f32
#define SMEM_BYTES 124416

// ============================ PTX helpers ============================
// D = A*B + D,  m16n8k16, fp16 inputs, fp32 accum.
__device__ __forceinline__ void mma16(float* d, const uint32_t* a,
                                      uint32_t b0, uint32_t b1) {
    asm volatile(
        "mma.sync.aligned.m16n8k16.row.col.f32.f16.f16.f32 "
        "{%0,%1,%2,%3}, {%4,%5,%6,%7}, {%8,%9}, {%0,%1,%2,%3};"
        : "+f"(d[0]), "+f"(d[1]), "+f"(d[2]), "+f"(d[3])
        : "r"(a[0]), "r"(a[1]), "r"(a[2]), "r"(a[3]), "r"(b0), "r"(b1));
}

__device__ __forceinline__ void ldsm4(uint32_t* r, uint32_t addr) {
    asm volatile(
        "ldmatrix.sync.aligned.m8n8.x4.shared.b16 {%0,%1,%2,%3}, [%4];"
        : "=r"(r[0]), "=r"(r[1]), "=r"(r[2]), "=r"(r[3]) : "r"(addr));
}

__device__ __forceinline__ uint32_t smem_u32(const void* p) {
    uint32_t a;
    asm("{ .reg .u64 t; cvta.to.shared.u64 t, %1; cvt.u32.u64 %0, t; }"
        : "=r"(a) : "l"(p));
    return a;
}

__device__ __forceinline__ uint32_t packh2(float a, float b) {
    __half2 h = __floats2half2_rn(a, b);
    return *reinterpret_cast<uint32_t*>(&h);
}

// ============================ kernel ============================
__global__ __launch_bounds__(NT, 1)
void patch_embed_mma(const float* __restrict__ xyz,
                     const float* __restrict__ centers,
                     const int*   __restrict__ idx_knn,
                     const float* __restrict__ W1,
                     const float* __restrict__ b1,
                     const float* __restrict__ W2,
                     const float* __restrict__ b2,
                     const float* __restrict__ W3,
                     const float* __restrict__ b3,
                     float*       __restrict__ out)
{
    extern __shared__ __align__(16) char smem[];
    __half* sW3h = reinterpret_cast<__half*>(smem + S_W3);
    __half* sHh  = reinterpret_cast<__half*>(smem + S_H);
    __half* sW2h = reinterpret_cast<__half*>(smem + S_W2);
    float*  sB2  = reinterpret_cast<float*>(smem + S_B2);
    float*  sW1v = reinterpret_cast<float*>(smem + S_W1);
    float*  sB1v = reinterpret_cast<float*>(smem + S_B1);

    const int tid  = threadIdx.x;
    const int lane = tid & 31;
    const int wid  = tid >> 5;
    const int gp   = lane >> 2;
    const int tg   = lane & 3;

    // warp tiling: mtp = 32-row quarter (== m_local), nq = n quarter
    const int mtp = wid & 3;
    const int nq  = wid >> 2;

    // ---- one-time staging: fp16 weights ------------------------------------
    for (int i = tid; i < 256 * 128; i += NT) {       // W3 [n=256][k=128]
        int n = i >> 7, k = i & 127;
        sW3h[n * PKH + k] = __float2half_rn(W3[i]);
    }
    for (int i = tid; i < 128 * 64; i += NT) {        // W2 [n=128][k=64]
        int n = i >> 6, k = i & 63;
        sW2h[n * PKW2 + k] = __float2half_rn(W2[i]);
    }
    if (tid < 192) sW1v[tid] = W1[tid];
    if (tid < 64)  sB1v[tid] = b1[tid];
    if (tid < 128) sB2[tid]  = b2[tid];
    __syncthreads();

    // ---- precomputed LDSM base addresses (bytes) ---------------------------
    const uint32_t sH_b  = smem_u32(sHh);
    const uint32_t sW3_b = smem_u32(sW3h);
    const uint32_t sW2_b = smem_u32(sW2h);
    // A (h): rows mtp*32 + m*16 + (lane&15), k-half (lane>>4)*8 halfs
    uint32_t aAddr[2];
    #pragma unroll
    for (int m = 0; m < 2; ++m)
        aAddr[m] = sH_b +
            (((mtp*32 + m*16 + (lane & 15)) * PKH + ((lane >> 4) << 3)) << 1);
    // B (W3): n = nq*64 + p*16 + (lane&7) + ((lane>>4)<<3); k-half ((lane>>3)&1)*8
    uint32_t b3Addr[4];
    #pragma unroll
    for (int p = 0; p < 4; ++p)
        b3Addr[p] = sW3_b +
            (((nq*64 + p*16 + (lane & 7) + ((lane >> 4) << 3)) * PKH
              + (((lane >> 3) & 1) << 3)) << 1);
    // B (W2): n = nq*32 + p*16 + ...
    uint32_t b2Addr[2];
    #pragma unroll
    for (int p = 0; p < 2; ++p)
        b2Addr[p] = sW2_b +
            (((nq*32 + p*16 + (lane & 7) + ((lane >> 4) << 3)) * PKW2
              + (((lane >> 3) & 1) << 3)) << 1);

    // ---- gather prefetch state (this thread's fixed row) -------------------
    const int row = tid & 127;                // m_local*32 + k
    const int cb  = (tid >> 7) * 16;          // 16-channel block
    const int kk  = row & 31;
    const int mo  = row >> 5;                 // m_local

    float px, py, pz;
    {
        const int bm = blockIdx.x * MT + mo;
        const int ii = __ldg(&idx_knn[bm * KNNk + kk]);
        const float* p = xyz + ((size_t)(bm >> 11) * Np + ii) * 3;
        px = p[0] - __ldg(&centers[bm * 3 + 0]);
        py = p[1] - __ldg(&centers[bm * 3 + 1]);
        pz = p[2] - __ldg(&centers[bm * 3 + 2]);
    }

    for (int g = blockIdx.x; g < NGROUPS; g += GRID) {
        const int bm0 = g * MT;
        const int gn  = (g + GRID < NGROUPS) ? (g + GRID) : g;

        // ---- layer 1: 3->64 relu (fp32 math, fp16 store) -> h1 -------------
        {
            uint32_t pk[8];
            #pragma unroll
            for (int j = 0; j < 8; ++j) {
                const int o0 = cb + 2*j;
                float v0 = sB1v[o0],     v1 = sB1v[o0 + 1];
                v0 = fmaf(sW1v[o0*3 + 0], px, v0);
                v1 = fmaf(sW1v[o0*3 + 3], px, v1);
                v0 = fmaf(sW1v[o0*3 + 1], py, v0);
                v1 = fmaf(sW1v[o0*3 + 4], py, v1);
                v0 = fmaf(sW1v[o0*3 + 2], pz, v0);
                v1 = fmaf(sW1v[o0*3 + 5], pz, v1);
                pk[j] = packh2(fmaxf(v0, 0.f), fmaxf(v1, 0.f));
            }
            uint32_t* h1r = reinterpret_cast<uint32_t*>(sHh + row * PKH + cb);
            *reinterpret_cast<uint4*>(h1r)     = make_uint4(pk[0], pk[1], pk[2], pk[3]);
            *reinterpret_cast<uint4*>(h1r + 4) = make_uint4(pk[4], pk[5], pk[6], pk[7]);
        }
        // prefetch next group's knn index (overlaps GEMM1)
        const int nbm = gn * MT + mo;
        const int nii = __ldg(&idx_knn[nbm * KNNk + kk]);
        __syncthreads();

        // ---- GEMM1: D1[128x128] = h1[128x64] * W2^T  (4 k16 steps) ---------
        {
            float acc1[2][4][4];
            #pragma unroll
            for (int m = 0; m < 2; ++m)
                #pragma unroll
                for (int nt = 0; nt < 4; ++nt)
                    #pragma unroll
                    for (int j = 0; j < 4; ++j) acc1[m][nt][j] = 0.f;

            #pragma unroll
            for (int ks = 0; ks < 4; ++ks) {
                const uint32_t k4 = (uint32_t)ks << 5;   // 16 halfs = 32 B
                uint32_t a0[4], a1[4];
                ldsm4(a0, aAddr[0] + k4);
                ldsm4(a1, aAddr[1] + k4);
                #pragma unroll
                for (int p = 0; p < 2; ++p) {
                    uint32_t bf[4];
                    ldsm4(bf, b2Addr[p] + k4);
                    mma16(acc1[0][2*p],     a0, bf[0], bf[1]);
                    mma16(acc1[1][2*p],     a1, bf[0], bf[1]);
                    mma16(acc1[0][2*p + 1], a0, bf[2], bf[3]);
                    mma16(acc1[1][2*p + 1], a1, bf[2], bf[3]);
                }
            }
            __syncthreads();   // all h1 reads done before h2 overwrites

            // ---- epilogue 1: h2 = fp16(relu(D1 + b2)) ----------------------
            #pragma unroll
            for (int m = 0; m < 2; ++m) {
                const int r0 = mtp*32 + m*16 + gp;
                #pragma unroll
                for (int nt = 0; nt < 4; ++nt) {
                    const int c0 = nq*32 + nt*8 + 2*tg;
                    const float bb0 = sB2[c0], bb1 = sB2[c0 + 1];
                    const uint32_t lo = packh2(fmaxf(acc1[m][nt][0] + bb0, 0.f),
                                               fmaxf(acc1[m][nt][1] + bb1, 0.f));
                    const uint32_t hi = packh2(fmaxf(acc1[m][nt][2] + bb0, 0.f),
                                               fmaxf(acc1[m][nt][3] + bb1, 0.f));
                    *reinterpret_cast<uint32_t*>(sHh + r0 * PKH + c0)       = lo;
                    *reinterpret_cast<uint32_t*>(sHh + (r0 + 8) * PKH + c0) = hi;
                }
            }
        }
        // prefetch next group's coords (overlaps GEMM2)
        {
            const float* p = xyz + ((size_t)(nbm >> 11) * Np + nii) * 3;
            px = p[0] - __ldg(&centers[nbm * 3 + 0]);
            py = p[1] - __ldg(&centers[nbm * 3 + 1]);
            pz = p[2] - __ldg(&centers[nbm * 3 + 2]);
        }
        __syncthreads();

        // ---- GEMM2: D2[128x256] = h2[128x128] * W3^T  (8 k16 steps) --------
        {
            float acc2[2][8][4];
            #pragma unroll
            for (int m = 0; m < 2; ++m)
                #pragma unroll
                for (int nt = 0; nt < 8; ++nt)
                    #pragma unroll
                    for (int j = 0; j < 4; ++j) acc2[m][nt][j] = 0.f;

            #pragma unroll
            for (int ks = 0; ks < 8; ++ks) {
                const uint32_t k4 = (uint32_t)ks << 5;
                uint32_t a0[4], a1[4];
                ldsm4(a0, aAddr[0] + k4);
                ldsm4(a1, aAddr[1] + k4);
                #pragma unroll
                for (int p = 0; p < 4; ++p) {
                    uint32_t bf[4];
                    ldsm4(bf, b3Addr[p] + k4);
                    mma16(acc2[0][2*p],     a0, bf[0], bf[1]);
                    mma16(acc2[1][2*p],     a1, bf[0], bf[1]);
                    mma16(acc2[0][2*p + 1], a0, bf[2], bf[3]);
                    mma16(acc2[1][2*p + 1], a1, bf[2], bf[3]);
                }
            }

            // ---- max over 32 k-rows of this warp's m_local + b3 + store ----
            const int bm = bm0 + mtp;
            #pragma unroll
            for (int nt = 0; nt < 8; ++nt) {
                float m0 = fmaxf(fmaxf(acc2[0][nt][0], acc2[0][nt][2]),
                                 fmaxf(acc2[1][nt][0], acc2[1][nt][2]));
                float m1 = fmaxf(fmaxf(acc2[0][nt][1], acc2[0][nt][3]),
                                 fmaxf(acc2[1][nt][1], acc2[1][nt][3]));
                #pragma unroll
                for (int s = 4; s < 32; s <<= 1) {
                    m0 = fmaxf(m0, __shfl_xor_sync(0xffffffffu, m0, s));
                    m1 = fmaxf(m1, __shfl_xor_sync(0xffffffffu, m1, s));
                }
                if (lane < 4) {
                    const int c = nq*64 + nt*8 + 2*tg;
                    float2 r2;
                    r2.x = m0 + __ldg(&b3[c]);
                    r2.y = m1 + __ldg(&b3[c + 1]);
                    *reinterpret_cast<float2*>(&out[(size_t)bm * EMBc + c]) = r2;
                }
            }
        }
        __syncthreads();   // GEMM2 reads of sH done before next layer-1 write
    }
}

// ============================ launch ============================
extern "C" void kernel_launch(void* const* d_in, const int* in_sizes, int n_in,
                              void* d_out, int out_size)
{
    // metadata order: xyz, centers, idx_knn, W1, b1, W2, b2, W3, b3
    const float* xyz     = (const float*)d_in[0];
    const float* centers = (const float*)d_in[1];
    const int*   idx_knn = (const int*)  d_in[2];
    const float* W1      = (const float*)d_in[3];
    const float* b1      = (const float*)d_in[4];
    const float* W2      = (const float*)d_in[5];
    const float* b2      = (const float*)d_in[6];
    const float* W3      = (const float*)d_in[7];
    const float* b3      = (const float*)d_in[8];
    float* out = (float*)d_out;

    // Idempotent attribute set (capture-safe, no allocation).
    cudaFuncSetAttribute(patch_embed_mma,
                         cudaFuncAttributeMaxDynamicSharedMemorySize,
                         SMEM_BYTES);

    patch_embed_mma<<<GRID, NT, SMEM_BYTES>>>(
        xyz, centers, idx_knn, W1, b1, W2, b2, W3, b3, out);
}

// round 9
// speedup vs baseline: 2.0575x; 1.6489x over previous
#include <cuda_runtime.h>
#include <cuda_fp16.h>
#include <cstdint>

// ============================ problem constants ============================
#define Bn      8
#define Np      16384
#define MCc     2048
#define KNNk    32
#define EMBc    256
#define MT      4                 // m-tiles per group (M = 128 rows)
#define NGROUPS (Bn * MCc / MT)   // 4096
#define GRID    152
#define NT      512

// Strides in halfs, padded so (PK mod 64) == 8 -> row byte-stride mod 128
// == 16 -> ldmatrix 8-row sets conflict-free.
#define PKH  136                  // h2 and W3 k-stride (K=128)
#define PKW  72                   // h1 and W2 k-stride (K=64)

// SMEM byte offsets (all 16B aligned)
#define S_W3  0                              // [256][136] half: 69632 B
#define S_H2  69632                          // [128][136] half: 34816 B
#define S_H1  104448                         // [128][72]  half: 18432 B
#define S_W2  122880                         // [128][72]  half: 18432 B
#define S_B2  141312                         // 128 f32
#define S_W1  141824                         // 192 f32
#define S_B1  142592                         // 64 f32
#define SMEM_BYTES 142848

// ============================ PTX helpers ============================
__device__ __forceinline__ void mma16(float* d, const uint32_t* a,
                                      uint32_t b0, uint32_t b1) {
    asm volatile(
        "mma.sync.aligned.m16n8k16.row.col.f32.f16.f16.f32 "
        "{%0,%1,%2,%3}, {%4,%5,%6,%7}, {%8,%9}, {%0,%1,%2,%3};"
        : "+f"(d[0]), "+f"(d[1]), "+f"(d[2]), "+f"(d[3])
        : "r"(a[0]), "r"(a[1]), "r"(a[2]), "r"(a[3]), "r"(b0), "r"(b1));
}

__device__ __forceinline__ void ldsm4(uint32_t* r, uint32_t addr) {
    asm volatile(
        "ldmatrix.sync.aligned.m8n8.x4.shared.b16 {%0,%1,%2,%3}, [%4];"
        : "=r"(r[0]), "=r"(r[1]), "=r"(r[2]), "=r"(r[3]) : "r"(addr));
}

__device__ __forceinline__ uint32_t smem_u32(const void* p) {
    uint32_t a;
    asm("{ .reg .u64 t; cvta.to.shared.u64 t, %1; cvt.u32.u64 %0, t; }"
        : "=r"(a) : "l"(p));
    return a;
}

__device__ __forceinline__ uint32_t packh2(float a, float b) {
    __half2 h = __floats2half2_rn(a, b);
    return *reinterpret_cast<uint32_t*>(&h);
}

// quad-local barrier: 4 warps sharing one m-block (128 threads)
__device__ __forceinline__ void quad_bar(int id) {
    asm volatile("bar.sync %0, %1;" :: "r"(id), "r"(128) : "memory");
}

// ============================ kernel ============================
__global__ __launch_bounds__(NT, 1)
void patch_embed_mma(const float* __restrict__ xyz,
                     const float* __restrict__ centers,
                     const int*   __restrict__ idx_knn,
                     const float* __restrict__ W1,
                     const float* __restrict__ b1,
                     const float* __restrict__ W2,
                     const float* __restrict__ b2,
                     const float* __restrict__ W3,
                     const float* __restrict__ b3,
                     float*       __restrict__ out)
{
    extern __shared__ __align__(16) char smem[];
    __half* sW3h = reinterpret_cast<__half*>(smem + S_W3);
    __half* sH2h = reinterpret_cast<__half*>(smem + S_H2);
    __half* sH1h = reinterpret_cast<__half*>(smem + S_H1);
    __half* sW2h = reinterpret_cast<__half*>(smem + S_W2);
    float*  sB2  = reinterpret_cast<float*>(smem + S_B2);
    float*  sW1v = reinterpret_cast<float*>(smem + S_W1);
    float*  sB1v = reinterpret_cast<float*>(smem + S_B1);

    const int tid  = threadIdx.x;
    const int lane = tid & 31;
    const int wid  = tid >> 5;
    const int gp   = lane >> 2;
    const int tg   = lane & 3;

    // quad pipelines: mtp = m-block (quad id), nq = n quarter within quad.
    // Quad warps (4*mtp .. 4*mtp+3) sit on DIFFERENT SMSPs -> cross-quad
    // overlap keeps every SMSP's tensor unit fed.
    const int mtp = wid >> 2;
    const int nq  = wid & 3;
    const int bar = mtp + 1;          // named barrier id (0 = __syncthreads)

    // ---- one-time staging: fp16 weights ------------------------------------
    for (int i = tid; i < 256 * 128; i += NT) {       // W3 [n=256][k=128]
        int n = i >> 7, k = i & 127;
        sW3h[n * PKH + k] = __float2half_rn(W3[i]);
    }
    for (int i = tid; i < 128 * 64; i += NT) {        // W2 [n=128][k=64]
        int n = i >> 6, k = i & 63;
        sW2h[n * PKW + k] = __float2half_rn(W2[i]);
    }
    if (tid < 192) sW1v[tid] = W1[tid];
    if (tid < 64)  sB1v[tid] = b1[tid];
    if (tid < 128) sB2[tid]  = b2[tid];
    __syncthreads();

    // ---- precomputed LDSM base addresses (bytes) ---------------------------
    const uint32_t sH1_b = smem_u32(sH1h);
    const uint32_t sH2_b = smem_u32(sH2h);
    const uint32_t sW3_b = smem_u32(sW3h);
    const uint32_t sW2_b = smem_u32(sW2h);
    // A frags: rows mtp*32 + m*16 + (lane&15), k-half (lane>>4)*8 halfs
    uint32_t a1Addr[2], a2Addr[2];
    #pragma unroll
    for (int m = 0; m < 2; ++m) {
        const int r = mtp*32 + m*16 + (lane & 15);
        const int kh = (lane >> 4) << 3;
        a1Addr[m] = sH1_b + ((r * PKW + kh) << 1);
        a2Addr[m] = sH2_b + ((r * PKH + kh) << 1);
    }
    // B (W3): n = nq*64 + p*16 + (lane&7) + ((lane>>4)<<3); k-half ((lane>>3)&1)*8
    uint32_t b3Addr[4];
    #pragma unroll
    for (int p = 0; p < 4; ++p)
        b3Addr[p] = sW3_b +
            (((nq*64 + p*16 + (lane & 7) + ((lane >> 4) << 3)) * PKH
              + (((lane >> 3) & 1) << 3)) << 1);
    // B (W2): n = nq*32 + p*16 + ...
    uint32_t b2Addr[2];
    #pragma unroll
    for (int p = 0; p < 2; ++p)
        b2Addr[p] = sW2_b +
            (((nq*32 + p*16 + (lane & 7) + ((lane >> 4) << 3)) * PKW
              + (((lane >> 3) & 1) << 3)) << 1);

    // ---- gather state: this thread's fixed row = mtp*32 + lane -------------
    const int row = mtp * 32 + lane;          // quad-local layer-1 row
    const int cb  = nq * 16;                  // 16-channel block

    float px, py, pz;
    {
        const int bm = blockIdx.x * MT + mtp;
        const int ii = __ldg(&idx_knn[bm * KNNk + lane]);
        const float* p = xyz + ((size_t)(bm >> 11) * Np + ii) * 3;
        px = p[0] - __ldg(&centers[bm * 3 + 0]);
        py = p[1] - __ldg(&centers[bm * 3 + 1]);
        pz = p[2] - __ldg(&centers[bm * 3 + 2]);
    }

    for (int g = blockIdx.x; g < NGROUPS; g += GRID) {
        const int bm0 = g * MT;
        const int gn  = (g + GRID < NGROUPS) ? (g + GRID) : g;

        // ---- layer 1: 3->64 relu (fp32 math, fp16 store) -> h1 -------------
        {
            uint32_t pk[8];
            #pragma unroll
            for (int j = 0; j < 8; ++j) {
                const int o0 = cb + 2*j;
                float v0 = sB1v[o0],     v1 = sB1v[o0 + 1];
                v0 = fmaf(sW1v[o0*3 + 0], px, v0);
                v1 = fmaf(sW1v[o0*3 + 3], px, v1);
                v0 = fmaf(sW1v[o0*3 + 1], py, v0);
                v1 = fmaf(sW1v[o0*3 + 4], py, v1);
                v0 = fmaf(sW1v[o0*3 + 2], pz, v0);
                v1 = fmaf(sW1v[o0*3 + 5], pz, v1);
                pk[j] = packh2(fmaxf(v0, 0.f), fmaxf(v1, 0.f));
            }
            uint32_t* h1r = reinterpret_cast<uint32_t*>(sH1h + row * PKW + cb);
            *reinterpret_cast<uint4*>(h1r)     = make_uint4(pk[0], pk[1], pk[2], pk[3]);
            *reinterpret_cast<uint4*>(h1r + 4) = make_uint4(pk[4], pk[5], pk[6], pk[7]);
        }
        // prefetch next group's knn index (overlaps GEMM1)
        const int nbm = gn * MT + mtp;
        const int nii = __ldg(&idx_knn[nbm * KNNk + lane]);

        quad_bar(bar);   // quad's h1 writes visible; prior GEMM2 reads done

        // ---- GEMM1: D1[m-block x 128] = h1 * W2^T  (4 k16 steps) -----------
        {
            float acc1[2][4][4];
            #pragma unroll
            for (int m = 0; m < 2; ++m)
                #pragma unroll
                for (int nt = 0; nt < 4; ++nt)
                    #pragma unroll
                    for (int j = 0; j < 4; ++j) acc1[m][nt][j] = 0.f;

            #pragma unroll
            for (int ks = 0; ks < 4; ++ks) {
                const uint32_t k4 = (uint32_t)ks << 5;   // 16 halfs = 32 B
                uint32_t a0[4], a1[4];
                ldsm4(a0, a1Addr[0] + k4);
                ldsm4(a1, a1Addr[1] + k4);
                #pragma unroll
                for (int p = 0; p < 2; ++p) {
                    uint32_t bf[4];
                    ldsm4(bf, b2Addr[p] + k4);
                    mma16(acc1[0][2*p],     a0, bf[0], bf[1]);
                    mma16(acc1[1][2*p],     a1, bf[0], bf[1]);
                    mma16(acc1[0][2*p + 1], a0, bf[2], bf[3]);
                    mma16(acc1[1][2*p + 1], a1, bf[2], bf[3]);
                }
            }

            // ---- epilogue 1: h2 = fp16(relu(D1 + b2)) (separate buffer) ----
            #pragma unroll
            for (int m = 0; m < 2; ++m) {
                const int r0 = mtp*32 + m*16 + gp;
                #pragma unroll
                for (int nt = 0; nt < 4; ++nt) {
                    const int c0 = nq*32 + nt*8 + 2*tg;
                    const float bb0 = sB2[c0], bb1 = sB2[c0 + 1];
                    const uint32_t lo = packh2(fmaxf(acc1[m][nt][0] + bb0, 0.f),
                                               fmaxf(acc1[m][nt][1] + bb1, 0.f));
                    const uint32_t hi = packh2(fmaxf(acc1[m][nt][2] + bb0, 0.f),
                                               fmaxf(acc1[m][nt][3] + bb1, 0.f));
                    *reinterpret_cast<uint32_t*>(sH2h + r0 * PKH + c0)       = lo;
                    *reinterpret_cast<uint32_t*>(sH2h + (r0 + 8) * PKH + c0) = hi;
                }
            }
        }
        // prefetch next group's coords (overlaps GEMM2)
        {
            const float* p = xyz + ((size_t)(nbm >> 11) * Np + nii) * 3;
            px = p[0] - __ldg(&centers[nbm * 3 + 0]);
            py = p[1] - __ldg(&centers[nbm * 3 + 1]);
            pz = p[2] - __ldg(&centers[nbm * 3 + 2]);
        }

        quad_bar(bar);   // quad's h2 writes visible; h1 reads done

        // ---- GEMM2: D2[m-block x 256] = h2 * W3^T  (8 k16 steps) -----------
        {
            float acc2[2][8][4];
            #pragma unroll
            for (int m = 0; m < 2; ++m)
                #pragma unroll
                for (int nt = 0; nt < 8; ++nt)
                    #pragma unroll
                    for (int j = 0; j < 4; ++j) acc2[m][nt][j] = 0.f;

            #pragma unroll
            for (int ks = 0; ks < 8; ++ks) {
                const uint32_t k4 = (uint32_t)ks << 5;
                uint32_t a0[4], a1[4];
                ldsm4(a0, a2Addr[0] + k4);
                ldsm4(a1, a2Addr[1] + k4);
                #pragma unroll
                for (int p = 0; p < 4; ++p) {
                    uint32_t bf[4];
                    ldsm4(bf, b3Addr[p] + k4);
                    mma16(acc2[0][2*p],     a0, bf[0], bf[1]);
                    mma16(acc2[1][2*p],     a1, bf[0], bf[1]);
                    mma16(acc2[0][2*p + 1], a0, bf[2], bf[3]);
                    mma16(acc2[1][2*p + 1], a1, bf[2], bf[3]);
                }
            }

            // ---- max over 32 k-rows of this warp's m-block + b3 + store ----
            const int bm = bm0 + mtp;
            #pragma unroll
            for (int nt = 0; nt < 8; ++nt) {
                float m0 = fmaxf(fmaxf(acc2[0][nt][0], acc2[0][nt][2]),
                                 fmaxf(acc2[1][nt][0], acc2[1][nt][2]));
                float m1 = fmaxf(fmaxf(acc2[0][nt][1], acc2[0][nt][3]),
                                 fmaxf(acc2[1][nt][1], acc2[1][nt][3]));
                #pragma unroll
                for (int s = 4; s < 32; s <<= 1) {
                    m0 = fmaxf(m0, __shfl_xor_sync(0xffffffffu, m0, s));
                    m1 = fmaxf(m1, __shfl_xor_sync(0xffffffffu, m1, s));
                }
                if (lane < 4) {
                    const int c = nq*64 + nt*8 + 2*tg;
                    float2 r2;
                    r2.x = m0 + __ldg(&b3[c]);
                    r2.y = m1 + __ldg(&b3[c + 1]);
                    *reinterpret_cast<float2*>(&out[(size_t)bm * EMBc + c]) = r2;
                }
            }
        }
        // no barrier here: next layer-1 writes h1, whose quad readers are
        // fenced by the first quad_bar of the next iteration.
    }
}

// ============================ launch ============================
extern "C" void kernel_launch(void* const* d_in, const int* in_sizes, int n_in,
                              void* d_out, int out_size)
{
    // metadata order: xyz, centers, idx_knn, W1, b1, W2, b2, W3, b3
    const float* xyz     = (const float*)d_in[0];
    const float* centers = (const float*)d_in[1];
    const int*   idx_knn = (const int*)  d_in[2];
    const float* W1      = (const float*)d_in[3];
    const float* b1      = (const float*)d_in[4];
    const float* W2      = (const float*)d_in[5];
    const float* b2      = (const float*)d_in[6];
    const float* W3      = (const float*)d_in[7];
    const float* b3      = (const float*)d_in[8];
    float* out = (float*)d_out;

    // Idempotent attribute set (capture-safe, no allocation).
    cudaFuncSetAttribute(patch_embed_mma,
                         cudaFuncAttributeMaxDynamicSharedMemorySize,
                         SMEM_BYTES);

    patch_embed_mma<<<GRID, NT, SMEM_BYTES>>>(
        xyz, centers, idx_knn, W1, b1, W2, b2, W3, b3, out);
}